// round 15
// baseline (speedup 1.0000x reference)
#include <cuda_runtime.h>
#include <cuda_bf16.h>
#include <math.h>

#define B_ 4
#define V_ 50000
#define C_ 256
#define K_ 128
#define LAMBDA 100.0f
#define NCHUNK 18
#define TPC 174
#define NTILES 3125
#define LDI 129

__device__ float g_part1[(size_t)NCHUNK * 8 * K_ * C_];
__device__ float g_A[8 * K_ * C_];
__device__ float g_AA2[2 * 2 * B_ * K_ * K_];
__device__ float g_Lc[B_ * K_ * K_];
__device__ float g_invd[B_ * K_];

__device__ __forceinline__ unsigned smem_u32(const void* p) {
    unsigned a;
    asm("{ .reg .u64 t; cvta.to.shared.u64 t, %1; cvt.u32.u64 %0, t; }" : "=r"(a) : "l"(p));
    return a;
}
__device__ __forceinline__ void cvt2(float x, float y, unsigned& hi, unsigned& lo) {
    __nv_bfloat162 h = __floats2bfloat162_rn(x, y);
    __nv_bfloat162 l = __floats2bfloat162_rn(x - __bfloat162float(h.x),
                                             y - __bfloat162float(h.y));
    hi = *(unsigned*)&h;
    lo = *(unsigned*)&l;
}
__device__ __forceinline__ void ldx4(unsigned* r, unsigned a) {
    asm volatile("ldmatrix.sync.aligned.m8n8.x4.shared.b16 {%0,%1,%2,%3}, [%4];"
                 : "=r"(r[0]), "=r"(r[1]), "=r"(r[2]), "=r"(r[3]) : "r"(a));
}
__device__ __forceinline__ void ldx2t(unsigned* r, unsigned a) {
    asm volatile("ldmatrix.sync.aligned.m8n8.x2.trans.shared.b16 {%0,%1}, [%2];"
                 : "=r"(r[0]), "=r"(r[1]) : "r"(a));
}
__device__ __forceinline__ void mma16816(float* d, const unsigned* a, const unsigned* b) {
    asm volatile("mma.sync.aligned.m16n8k16.row.col.f32.bf16.bf16.f32 "
                 "{%0,%1,%2,%3}, {%4,%5,%6,%7}, {%8,%9}, {%0,%1,%2,%3};"
                 : "+f"(d[0]), "+f"(d[1]), "+f"(d[2]), "+f"(d[3])
                 : "r"(a[0]), "r"(a[1]), "r"(a[2]), "r"(a[3]), "r"(b[0]), "r"(b[1]));
}

// ---------------------------------------------------------------------------
// GEMM1 via mma.sync bf16 hi/lo split (3 passes, single fp32 accumulator).
// Double-buffered smem: one __syncthreads per tile; LDG(t+1) -> MMA(t) ->
// cvt+STS(t+1) overlapped with other warps' MMAs.
// ---------------------------------------------------------------------------
__global__ __launch_bounds__(256, 2)
void gemm1_mma(const float* __restrict__ fx, const float* __restrict__ fy,
               const float* __restrict__ ex, const float* __restrict__ ey)
{
    __shared__ __align__(16) __nv_bfloat16 Ah[2][128 * 24], Al[2][128 * 24]; // stride 48B
    __shared__ __align__(16) __nv_bfloat16 Bh[2][16 * 136], Bl[2][16 * 136]; // stride 272B

    const int chunk = blockIdx.x, ntile = blockIdx.y, p = blockIdx.z;
    const int b = p >> 1, which = p & 1;
    const float* E = (which ? ey : ex) + (size_t)b * K_ * V_;
    const float* F = (which ? fy : fx) + (size_t)b * V_ * C_ + ntile * 128;
    float* out = g_part1 + ((size_t)chunk * 8 + which * 4 + b) * K_ * C_ + ntile * 128;

    const int tid = threadIdx.x, wid = tid >> 5, lane = tid & 31;
    const int wm = (wid >> 1) * 32, wn = (wid & 1) * 64;

    const int ar = tid >> 1, ahalf = tid & 1;
    const int fv = tid >> 4, fc = (tid & 15) * 8;

    const unsigned aAh = smem_u32(Ah), aAl = smem_u32(Al);
    const unsigned aBh = smem_u32(Bh), aBl = smem_u32(Bl);
    const unsigned ABUF = 128 * 24 * 2;   // bytes per A buffer
    const unsigned BBUF = 16 * 136 * 2;   // bytes per B buffer

    float acc[2][8][4];
#pragma unroll
    for (int mt = 0; mt < 2; ++mt)
#pragma unroll
        for (int nt = 0; nt < 8; ++nt)
#pragma unroll
            for (int e = 0; e < 4; ++e) acc[mt][nt][e] = 0.0f;

    const unsigned aoffH0 = aAh + (wm + (lane & 15)) * 48 + (lane >> 4) * 16;
    const unsigned aoffL0 = aAl + (wm + (lane & 15)) * 48 + (lane >> 4) * 16;
    const unsigned brow = (lane & 15);

    const int t0 = chunk * TPC;
    const int t1 = (t0 + TPC < NTILES) ? (t0 + TPC) : NTILES;

    const float* Ebase = E + (size_t)ar * V_ + ahalf * 8;

    // prologue: stage tile t0 into buffer 0
    {
        const int vb = t0 << 4;
        float4 e0 = *(const float4*)(Ebase + vb);
        float4 e1 = *(const float4*)(Ebase + vb + 4);
        const float* Fp = F + (size_t)(vb + fv) * C_ + fc;
        float4 f0 = *(const float4*)(Fp);
        float4 f1 = *(const float4*)(Fp + 4);
        unsigned h[4], l[4];
        cvt2(e0.x, e0.y, h[0], l[0]); cvt2(e0.z, e0.w, h[1], l[1]);
        cvt2(e1.x, e1.y, h[2], l[2]); cvt2(e1.z, e1.w, h[3], l[3]);
        *(uint4*)((char*)Ah[0] + ar * 48 + ahalf * 16) = make_uint4(h[0], h[1], h[2], h[3]);
        *(uint4*)((char*)Al[0] + ar * 48 + ahalf * 16) = make_uint4(l[0], l[1], l[2], l[3]);
        cvt2(f0.x, f0.y, h[0], l[0]); cvt2(f0.z, f0.w, h[1], l[1]);
        cvt2(f1.x, f1.y, h[2], l[2]); cvt2(f1.z, f1.w, h[3], l[3]);
        *(uint4*)((char*)Bh[0] + fv * 272 + fc * 2) = make_uint4(h[0], h[1], h[2], h[3]);
        *(uint4*)((char*)Bl[0] + fv * 272 + fc * 2) = make_uint4(l[0], l[1], l[2], l[3]);
    }
    __syncthreads();

    for (int t = t0; t < t1; ++t) {
        const int buf = (t - t0) & 1;
        const bool more = (t + 1 < t1);

        float4 e0, e1, f0, f1;
        if (more) {
            const int vb = (t + 1) << 4;
            e0 = *(const float4*)(Ebase + vb);
            e1 = *(const float4*)(Ebase + vb + 4);
            const float* Fp = F + (size_t)(vb + fv) * C_ + fc;
            f0 = *(const float4*)(Fp);
            f1 = *(const float4*)(Fp + 4);
        }

        // MMAs from current buffer
        {
            const unsigned aoffH = aoffH0 + buf * ABUF;
            const unsigned aoffL = aoffL0 + buf * ABUF;
            unsigned ahf[2][4], alf[2][4];
            ldx4(ahf[0], aoffH);
            ldx4(ahf[1], aoffH + 16 * 48);
            ldx4(alf[0], aoffL);
            ldx4(alf[1], aoffL + 16 * 48);
#pragma unroll
            for (int nt = 0; nt < 8; ++nt) {
                const unsigned boff = buf * BBUF + brow * 272 + (wn + nt * 8) * 2;
                unsigned bh[2], bl[2];
                ldx2t(bh, aBh + boff);
                ldx2t(bl, aBl + boff);
#pragma unroll
                for (int mt = 0; mt < 2; ++mt) {
                    mma16816(acc[mt][nt], ahf[mt], bh);
                    mma16816(acc[mt][nt], ahf[mt], bl);
                    mma16816(acc[mt][nt], alf[mt], bh);
                }
            }
        }

        // stage tile t+1 into the other buffer
        if (more) {
            const int nb = buf ^ 1;
            unsigned h[4], l[4];
            cvt2(e0.x, e0.y, h[0], l[0]); cvt2(e0.z, e0.w, h[1], l[1]);
            cvt2(e1.x, e1.y, h[2], l[2]); cvt2(e1.z, e1.w, h[3], l[3]);
            *(uint4*)((char*)Ah[nb] + ar * 48 + ahalf * 16) = make_uint4(h[0], h[1], h[2], h[3]);
            *(uint4*)((char*)Al[nb] + ar * 48 + ahalf * 16) = make_uint4(l[0], l[1], l[2], l[3]);
            cvt2(f0.x, f0.y, h[0], l[0]); cvt2(f0.z, f0.w, h[1], l[1]);
            cvt2(f1.x, f1.y, h[2], l[2]); cvt2(f1.z, f1.w, h[3], l[3]);
            *(uint4*)((char*)Bh[nb] + fv * 272 + fc * 2) = make_uint4(h[0], h[1], h[2], h[3]);
            *(uint4*)((char*)Bl[nb] + fv * 272 + fc * 2) = make_uint4(l[0], l[1], l[2], l[3]);
        }
        __syncthreads();
    }

#pragma unroll
    for (int mt = 0; mt < 2; ++mt)
#pragma unroll
        for (int nt = 0; nt < 8; ++nt) {
            const int row = wm + mt * 16 + (lane >> 2);
            const int col = wn + nt * 8 + (lane & 3) * 2;
            *(float2*)(out + (size_t)row * C_ + col) =
                make_float2(acc[mt][nt][0], acc[mt][nt][1]);
            *(float2*)(out + (size_t)(row + 8) * C_ + col) =
                make_float2(acc[mt][nt][2], acc[mt][nt][3]);
        }
}

__global__ void reduceA()
{
    const int i = blockIdx.x * 256 + threadIdx.x;
    float s = 0.0f;
#pragma unroll
    for (int c = 0; c < NCHUNK; ++c) s += g_part1[(size_t)c * 8 * K_ * C_ + i];
    g_A[i] = s;
}

__global__ __launch_bounds__(256, 2)
void gemm2()
{
    const int cc = blockIdx.x;
    const int t = blockIdx.y & 1, b = blockIdx.y >> 1;
    const float* P = g_A + ((size_t)(t * B_ + b) * K_) * C_ + cc * 128;
    const float* Q = g_A + ((size_t)b * K_) * C_ + cc * 128;
    float* out = g_AA2 + ((size_t)((cc * 2 + t) * B_ + b) * K_) * K_;

    __shared__ float Ps[16][132];
    __shared__ float Qs[16][132];
    const int tid = threadIdx.x;
    const int lk = tid >> 1, lq = tid & 1;
    const int tm = tid >> 4, tn = tid & 15;

    float acc[8][8];
#pragma unroll
    for (int i = 0; i < 8; ++i)
#pragma unroll
        for (int j = 0; j < 8; ++j) acc[i][j] = 0.0f;

    for (int kt = 0; kt < 8; ++kt) {
        const int c = kt << 4;
        float4 p0 = *(const float4*)(P + (size_t)lk * C_ + c + (lq << 2));
        float4 p1 = *(const float4*)(P + (size_t)lk * C_ + c + (lq << 2) + 8);
        float4 q0 = *(const float4*)(Q + (size_t)lk * C_ + c + (lq << 2));
        float4 q1 = *(const float4*)(Q + (size_t)lk * C_ + c + (lq << 2) + 8);
        __syncthreads();
        const int r0 = lq << 2;
        Ps[r0 + 0][lk] = p0.x; Ps[r0 + 1][lk] = p0.y; Ps[r0 + 2][lk] = p0.z; Ps[r0 + 3][lk] = p0.w;
        Ps[r0 + 8][lk] = p1.x; Ps[r0 + 9][lk] = p1.y; Ps[r0 + 10][lk] = p1.z; Ps[r0 + 11][lk] = p1.w;
        Qs[r0 + 0][lk] = q0.x; Qs[r0 + 1][lk] = q0.y; Qs[r0 + 2][lk] = q0.z; Qs[r0 + 3][lk] = q0.w;
        Qs[r0 + 8][lk] = q1.x; Qs[r0 + 9][lk] = q1.y; Qs[r0 + 10][lk] = q1.z; Qs[r0 + 11][lk] = q1.w;
        __syncthreads();
#pragma unroll
        for (int vv = 0; vv < 16; ++vv) {
            float4 a0 = *(const float4*)&Ps[vv][tm << 2];
            float4 a1 = *(const float4*)&Ps[vv][64 + (tm << 2)];
            float4 b0 = *(const float4*)&Qs[vv][tn << 2];
            float4 b1 = *(const float4*)&Qs[vv][64 + (tn << 2)];
            float a[8] = {a0.x, a0.y, a0.z, a0.w, a1.x, a1.y, a1.z, a1.w};
            float bb[8] = {b0.x, b0.y, b0.z, b0.w, b1.x, b1.y, b1.z, b1.w};
#pragma unroll
            for (int i = 0; i < 8; ++i)
#pragma unroll
                for (int j = 0; j < 8; ++j) acc[i][j] += a[i] * bb[j];
        }
    }
#pragma unroll
    for (int i = 0; i < 8; ++i) {
        const int row = (i < 4) ? ((tm << 2) + i) : (64 + (tm << 2) + i - 4);
        float4 o0 = {acc[i][0], acc[i][1], acc[i][2], acc[i][3]};
        float4 o1 = {acc[i][4], acc[i][5], acc[i][6], acc[i][7]};
        *(float4*)(out + (size_t)row * K_ + (tn << 2)) = o0;
        *(float4*)(out + (size_t)row * K_ + 64 + (tn << 2)) = o1;
    }
}

// ---------------------------------------------------------------------------
// Blocked LDL^T (R11 variant): smem diag block (warp 0, syncwarp), panel in
// registers, 2x2-blocked trailing update.
// ---------------------------------------------------------------------------
__global__ __launch_bounds__(256, 1)
void factor()
{
    __shared__ float M[K_ * LDI];
    __shared__ float Wd[96 * 33];
    __shared__ float sinvd[K_];
    const int b = blockIdx.x, tid = threadIdx.x;

    const float* X0 = g_AA2 + ((size_t)(0 * B_ + b) * K_) * K_;
    const float* X1 = g_AA2 + ((size_t)(2 * B_ + b) * K_) * K_;
    for (int idx = tid; idx < K_ * K_; idx += 256) {
        const int m = idx >> 7, c = idx & 127;
        M[m * LDI + c] = X0[idx] + X1[idx];
    }
    __syncthreads();

#pragma unroll
    for (int kb = 0; kb < 4; ++kb) {
        const int j0 = kb << 5;
        if (tid < 32) {
            for (int j = 0; j < 32; ++j) {
                const float inv = __frcp_rn(M[(j0 + j) * LDI + j0 + j]);
                if (tid > j) {
                    const float cf = M[(j0 + tid) * LDI + j0 + j] * inv;
                    for (int l = j + 1; l <= tid; ++l)
                        M[(j0 + tid) * LDI + j0 + l] -= cf * M[(j0 + l) * LDI + j0 + j];
                }
                __syncwarp();
            }
            sinvd[j0 + tid] = __frcp_rn(M[(j0 + tid) * LDI + j0 + tid]);
        }
        __syncthreads();

        const int nrows = 96 - (kb << 5);
        if (nrows > 0) {
            if (tid < nrows) {
                const int i = j0 + 32 + tid;
                float w[32];
#pragma unroll
                for (int l = 0; l < 32; ++l) w[l] = M[i * LDI + j0 + l];
#pragma unroll
                for (int l = 0; l < 32; ++l) {
                    const float c = w[l] * sinvd[j0 + l];
#pragma unroll
                    for (int j = l + 1; j < 32; ++j)
                        w[j] -= c * M[(j0 + j) * LDI + j0 + l];
                }
#pragma unroll
                for (int l = 0; l < 32; ++l) {
                    M[i * LDI + j0 + l] = w[l] * sinvd[j0 + l];
                    Wd[tid * 33 + l] = w[l];
                }
            }
            __syncthreads();

            const int nb = nrows >> 1;
            for (int e = tid; e < nb * nb; e += 256) {
                const int rb = e / nb, cb = e % nb;
                if (cb <= rb) {
                    const int i0 = j0 + 32 + rb * 2, c0 = j0 + 32 + cb * 2;
                    float s00 = 0.f, s01 = 0.f, s10 = 0.f, s11 = 0.f;
#pragma unroll
                    for (int l = 0; l < 32; ++l) {
                        const float m0 = M[i0 * LDI + j0 + l];
                        const float m1 = M[(i0 + 1) * LDI + j0 + l];
                        const float w0 = Wd[(cb * 2) * 33 + l];
                        const float w1 = Wd[(cb * 2 + 1) * 33 + l];
                        s00 += m0 * w0; s01 += m0 * w1;
                        s10 += m1 * w0; s11 += m1 * w1;
                    }
                    M[i0 * LDI + c0]           -= s00;
                    M[i0 * LDI + c0 + 1]       -= s01;
                    M[(i0 + 1) * LDI + c0]     -= s10;
                    M[(i0 + 1) * LDI + c0 + 1] -= s11;
                }
            }
            __syncthreads();
        }
    }

    float* Lc = g_Lc + (size_t)b * K_ * K_;
    for (int idx = tid; idx < K_ * K_; idx += 256) {
        const int j = idx >> 7, r = idx & 127;
        float v;
        if (r < j)       v = 0.0f;
        else if (r == j) v = 1.0f;
        else if ((r >> 5) == (j >> 5)) v = M[r * LDI + j] * sinvd[j];
        else             v = M[r * LDI + j];
        Lc[idx] = v;
    }
    if (tid < K_) g_invd[b * K_ + tid] = sinvd[tid];
}

__global__ __launch_bounds__(128)
void bigsolve(const float* __restrict__ evx, const float* __restrict__ evy,
              float* __restrict__ outp)
{
    extern __shared__ float Ls[];
    __shared__ float sinvd[K_];

    const int b = blockIdx.x >> 5, grp = blockIdx.x & 31;
    const int tid = threadIdx.x, w = tid >> 5, k = tid & 31;
    const int i = grp * 4 + w;

    const float* Lc = g_Lc + (size_t)b * K_ * K_;
    for (int idx = tid; idx < K_ * K_; idx += 128) {
        const int j = idx >> 7, t = idx & 127;
        Ls[j * LDI + t] = Lc[idx];
    }
    if (tid < K_) sinvd[tid] = g_invd[b * K_ + tid];

    float r[4], d[4], x[4], invd_r[4];
    const float s = fmaxf(evx[b * K_ + K_ - 1], evy[b * K_ + K_ - 1]);
    const float g2 = sqrtf(evy[b * K_ + i] / s);
    const float h2 = 1.0f / (g2 * g2 + 1.0f);
    const float ya = g2 * h2, yb = h2;
    const float* Y0 = g_AA2 + ((size_t)(1 * B_ + b) * K_ + i) * K_;
    const float* Y1 = g_AA2 + ((size_t)(3 * B_ + b) * K_ + i) * K_;
#pragma unroll
    for (int m = 0; m < 4; ++m) {
        const int t = k + 32 * m;
        r[m] = Y0[t] + Y1[t];
        const float g1 = sqrtf(evx[b * K_ + t] / s);
        const float h1 = 1.0f / (g1 * g1 + 1.0f);
        const float re = ya - g1 * h1, im = yb - h1;
        d[m] = LAMBDA * (re * re + im * im);
        x[m] = 0.0f;
    }
    __syncthreads();
#pragma unroll
    for (int m = 0; m < 4; ++m) invd_r[m] = sinvd[k + 32 * m];

    for (int it = 0; it < 3; ++it) {
        float y[4];
#pragma unroll
        for (int m = 0; m < 4; ++m) y[m] = r[m] - d[m] * x[m];
#pragma unroll
        for (int q = 0; q < 4; ++q)
            for (int j2 = 0; j2 < 32; ++j2) {
                const int j = q * 32 + j2;
                const float yj = __shfl_sync(0xFFFFFFFFu, y[q], j2);
#pragma unroll
                for (int m = 0; m < 4; ++m)
                    if (m > q || (m == q && k > j2))
                        y[m] -= Ls[j * LDI + k + 32 * m] * yj;
            }
#pragma unroll
        for (int m = 0; m < 4; ++m) y[m] *= invd_r[m];
#pragma unroll
        for (int q = 3; q >= 0; --q)
            for (int j2 = 31; j2 >= 0; --j2) {
                const int j = q * 32 + j2;
                const float yj = __shfl_sync(0xFFFFFFFFu, y[q], j2);
#pragma unroll
                for (int m = 0; m < 4; ++m)
                    if (m < q || (m == q && k < j2))
                        y[m] -= Ls[(k + 32 * m) * LDI + j] * yj;
            }
#pragma unroll
        for (int m = 0; m < 4; ++m) x[m] = y[m];
    }
    float* o = outp + ((size_t)(b * K_ + i)) * K_;
#pragma unroll
    for (int m = 0; m < 4; ++m) o[k + 32 * m] = x[m];
}

extern "C" void kernel_launch(void* const* d_in, const int* in_sizes, int n_in,
                              void* d_out, int out_size)
{
    const float* fx  = (const float*)d_in[0];
    const float* fy  = (const float*)d_in[1];
    const float* evx = (const float*)d_in[2];
    const float* evy = (const float*)d_in[3];
    const float* ex  = (const float*)d_in[4];
    const float* ey  = (const float*)d_in[5];
    float* out = (float*)d_out;

    static int attr_done = 0;
    if (!attr_done) {
        cudaFuncSetAttribute(bigsolve, cudaFuncAttributeMaxDynamicSharedMemorySize,
                             K_ * LDI * (int)sizeof(float));
        attr_done = 1;
    }

    gemm1_mma<<<dim3(NCHUNK, 2, 8), 256>>>(fx, fy, ex, ey);
    reduceA<<<(8 * K_ * C_) / 256, 256>>>();
    gemm2<<<dim3(2, 8), 256>>>();
    factor<<<B_, 256>>>();
    bigsolve<<<B_ * 32, 128, K_ * LDI * sizeof(float)>>>(evx, evy, out);
}

// round 16
// speedup vs baseline: 1.0712x; 1.0712x over previous
#include <cuda_runtime.h>
#include <cuda_bf16.h>
#include <math.h>

#define B_ 4
#define V_ 50000
#define C_ 256
#define K_ 128
#define LAMBDA 100.0f
#define NCH 38
#define TPC 83            // 38*83 = 3154 >= 3125
#define NTILES 3125
#define LDI 129

__device__ float g_part1x[(size_t)NCH * 4 * K_ * C_];
__device__ float g_part1y[(size_t)NCH * 4 * K_ * C_];
__device__ float g_Ax[4 * K_ * C_];
__device__ float g_Ay[4 * K_ * C_];
__device__ float g_AA2[2 * 2 * B_ * K_ * K_];
__device__ float g_Lc[B_ * K_ * K_];
__device__ float g_invd[B_ * K_];

__device__ __forceinline__ unsigned smem_u32(const void* p) {
    unsigned a;
    asm("{ .reg .u64 t; cvta.to.shared.u64 t, %1; cvt.u32.u64 %0, t; }" : "=r"(a) : "l"(p));
    return a;
}
__device__ __forceinline__ void cvt2(float x, float y, unsigned& hi, unsigned& lo) {
    __nv_bfloat162 h = __floats2bfloat162_rn(x, y);
    __nv_bfloat162 l = __floats2bfloat162_rn(x - __bfloat162float(h.x),
                                             y - __bfloat162float(h.y));
    hi = *(unsigned*)&h;
    lo = *(unsigned*)&l;
}
__device__ __forceinline__ void ldx4(unsigned* r, unsigned a) {
    asm volatile("ldmatrix.sync.aligned.m8n8.x4.shared.b16 {%0,%1,%2,%3}, [%4];"
                 : "=r"(r[0]), "=r"(r[1]), "=r"(r[2]), "=r"(r[3]) : "r"(a));
}
__device__ __forceinline__ void ldx2t(unsigned* r, unsigned a) {
    asm volatile("ldmatrix.sync.aligned.m8n8.x2.trans.shared.b16 {%0,%1}, [%2];"
                 : "=r"(r[0]), "=r"(r[1]) : "r"(a));
}
__device__ __forceinline__ void mma16816(float* d, const unsigned* a, const unsigned* b) {
    asm volatile("mma.sync.aligned.m16n8k16.row.col.f32.bf16.bf16.f32 "
                 "{%0,%1,%2,%3}, {%4,%5,%6,%7}, {%8,%9}, {%0,%1,%2,%3};"
                 : "+f"(d[0]), "+f"(d[1]), "+f"(d[2]), "+f"(d[3])
                 : "r"(a[0]), "r"(a[1]), "r"(a[2]), "r"(a[3]), "r"(b[0]), "r"(b[1]));
}

// ---------------------------------------------------------------------------
// GEMM1 (one side: x or y) via mma.sync bf16 hi/lo split, R11 single-buffer
// pipeline (prefetch t+1 LDG before t's MMAs). grid (NCH, 2, 4).
// ---------------------------------------------------------------------------
__global__ __launch_bounds__(256, 2)
void gemm1_mma(const float* __restrict__ F_, const float* __restrict__ E_,
               float* __restrict__ part)
{
    __shared__ __align__(16) __nv_bfloat16 Ah[128 * 24], Al[128 * 24];   // stride 48B
    __shared__ __align__(16) __nv_bfloat16 Bh[16 * 136], Bl[16 * 136];   // stride 272B

    const int chunk = blockIdx.x, ntile = blockIdx.y, b = blockIdx.z;
    const float* E = E_ + (size_t)b * K_ * V_;
    const float* F = F_ + (size_t)b * V_ * C_ + ntile * 128;
    float* out = part + ((size_t)(chunk * 4 + b)) * K_ * C_ + ntile * 128;

    const int tid = threadIdx.x, wid = tid >> 5, lane = tid & 31;
    const int wm = (wid >> 1) * 32, wn = (wid & 1) * 64;

    const int ar = tid >> 1, ahalf = tid & 1;
    const int fv = tid >> 4, fc = (tid & 15) * 8;

    const unsigned aAh = smem_u32(Ah), aAl = smem_u32(Al);
    const unsigned aBh = smem_u32(Bh), aBl = smem_u32(Bl);

    float acc[2][8][4];
#pragma unroll
    for (int mt = 0; mt < 2; ++mt)
#pragma unroll
        for (int nt = 0; nt < 8; ++nt)
#pragma unroll
            for (int e = 0; e < 4; ++e) acc[mt][nt][e] = 0.0f;

    const unsigned aoffH0 = aAh + (wm + (lane & 15)) * 48 + (lane >> 4) * 16;
    const unsigned aoffL0 = aAl + (wm + (lane & 15)) * 48 + (lane >> 4) * 16;
    const unsigned brow = (lane & 15);

    const int t0 = chunk * TPC;
    const int t1 = (t0 + TPC < NTILES) ? (t0 + TPC) : NTILES;

    const float* Ebase = E + (size_t)ar * V_ + ahalf * 8;

    float4 e0, e1, f0, f1;
    {
        const int vb = t0 << 4;
        e0 = *(const float4*)(Ebase + vb);
        e1 = *(const float4*)(Ebase + vb + 4);
        const float* Fp = F + (size_t)(vb + fv) * C_ + fc;
        f0 = *(const float4*)(Fp);
        f1 = *(const float4*)(Fp + 4);
    }

    for (int t = t0; t < t1; ++t) {
        __syncthreads();
        {
            unsigned h[4], l[4];
            cvt2(e0.x, e0.y, h[0], l[0]); cvt2(e0.z, e0.w, h[1], l[1]);
            cvt2(e1.x, e1.y, h[2], l[2]); cvt2(e1.z, e1.w, h[3], l[3]);
            *(uint4*)((char*)Ah + ar * 48 + ahalf * 16) = make_uint4(h[0], h[1], h[2], h[3]);
            *(uint4*)((char*)Al + ar * 48 + ahalf * 16) = make_uint4(l[0], l[1], l[2], l[3]);
            cvt2(f0.x, f0.y, h[0], l[0]); cvt2(f0.z, f0.w, h[1], l[1]);
            cvt2(f1.x, f1.y, h[2], l[2]); cvt2(f1.z, f1.w, h[3], l[3]);
            *(uint4*)((char*)Bh + fv * 272 + fc * 2) = make_uint4(h[0], h[1], h[2], h[3]);
            *(uint4*)((char*)Bl + fv * 272 + fc * 2) = make_uint4(l[0], l[1], l[2], l[3]);
        }
        __syncthreads();

        if (t + 1 < t1) {
            const int vb = (t + 1) << 4;
            e0 = *(const float4*)(Ebase + vb);
            e1 = *(const float4*)(Ebase + vb + 4);
            const float* Fp = F + (size_t)(vb + fv) * C_ + fc;
            f0 = *(const float4*)(Fp);
            f1 = *(const float4*)(Fp + 4);
        }

        unsigned ahf[2][4], alf[2][4];
        ldx4(ahf[0], aoffH0);
        ldx4(ahf[1], aoffH0 + 16 * 48);
        ldx4(alf[0], aoffL0);
        ldx4(alf[1], aoffL0 + 16 * 48);
#pragma unroll
        for (int nt = 0; nt < 8; ++nt) {
            const unsigned boff = brow * 272 + (wn + nt * 8) * 2;
            unsigned bh[2], bl[2];
            ldx2t(bh, aBh + boff);
            ldx2t(bl, aBl + boff);
#pragma unroll
            for (int mt = 0; mt < 2; ++mt) {
                mma16816(acc[mt][nt], ahf[mt], bh);
                mma16816(acc[mt][nt], ahf[mt], bl);
                mma16816(acc[mt][nt], alf[mt], bh);
            }
        }
    }

#pragma unroll
    for (int mt = 0; mt < 2; ++mt)
#pragma unroll
        for (int nt = 0; nt < 8; ++nt) {
            const int row = wm + mt * 16 + (lane >> 2);
            const int col = wn + nt * 8 + (lane & 3) * 2;
            *(float2*)(out + (size_t)row * C_ + col) =
                make_float2(acc[mt][nt][0], acc[mt][nt][1]);
            *(float2*)(out + (size_t)(row + 8) * C_ + col) =
                make_float2(acc[mt][nt][2], acc[mt][nt][3]);
        }
}

__global__ void reduceHalf(const float* __restrict__ part, float* __restrict__ outA)
{
    const int i = blockIdx.x * 256 + threadIdx.x;   // 4*K_*C_ = 131072
    float s = 0.0f;
#pragma unroll
    for (int c = 0; c < NCH; ++c) s += part[(size_t)c * 4 * K_ * C_ + i];
    outA[i] = s;
}

// gemm2 for one t: t=0 -> AA_xx (P=Q=Ax), t=1 -> AA_yx (P=Ay, Q=Ax)
__global__ __launch_bounds__(256, 2)
void gemm2_t(int t)
{
    const int cc = blockIdx.x, b = blockIdx.y;
    const float* P = (t ? g_Ay : g_Ax) + ((size_t)b * K_) * C_ + cc * 128;
    const float* Q = g_Ax + ((size_t)b * K_) * C_ + cc * 128;
    float* out = g_AA2 + ((size_t)((cc * 2 + t) * B_ + b) * K_) * K_;

    __shared__ float Ps[16][132];
    __shared__ float Qs[16][132];
    const int tid = threadIdx.x;
    const int lk = tid >> 1, lq = tid & 1;
    const int tm = tid >> 4, tn = tid & 15;

    float acc[8][8];
#pragma unroll
    for (int i = 0; i < 8; ++i)
#pragma unroll
        for (int j = 0; j < 8; ++j) acc[i][j] = 0.0f;

    for (int kt = 0; kt < 8; ++kt) {
        const int c = kt << 4;
        float4 p0 = *(const float4*)(P + (size_t)lk * C_ + c + (lq << 2));
        float4 p1 = *(const float4*)(P + (size_t)lk * C_ + c + (lq << 2) + 8);
        float4 q0 = *(const float4*)(Q + (size_t)lk * C_ + c + (lq << 2));
        float4 q1 = *(const float4*)(Q + (size_t)lk * C_ + c + (lq << 2) + 8);
        __syncthreads();
        const int r0 = lq << 2;
        Ps[r0 + 0][lk] = p0.x; Ps[r0 + 1][lk] = p0.y; Ps[r0 + 2][lk] = p0.z; Ps[r0 + 3][lk] = p0.w;
        Ps[r0 + 8][lk] = p1.x; Ps[r0 + 9][lk] = p1.y; Ps[r0 + 10][lk] = p1.z; Ps[r0 + 11][lk] = p1.w;
        Qs[r0 + 0][lk] = q0.x; Qs[r0 + 1][lk] = q0.y; Qs[r0 + 2][lk] = q0.z; Qs[r0 + 3][lk] = q0.w;
        Qs[r0 + 8][lk] = q1.x; Qs[r0 + 9][lk] = q1.y; Qs[r0 + 10][lk] = q1.z; Qs[r0 + 11][lk] = q1.w;
        __syncthreads();
#pragma unroll
        for (int vv = 0; vv < 16; ++vv) {
            float4 a0 = *(const float4*)&Ps[vv][tm << 2];
            float4 a1 = *(const float4*)&Ps[vv][64 + (tm << 2)];
            float4 b0 = *(const float4*)&Qs[vv][tn << 2];
            float4 b1 = *(const float4*)&Qs[vv][64 + (tn << 2)];
            float a[8] = {a0.x, a0.y, a0.z, a0.w, a1.x, a1.y, a1.z, a1.w};
            float bb[8] = {b0.x, b0.y, b0.z, b0.w, b1.x, b1.y, b1.z, b1.w};
#pragma unroll
            for (int i = 0; i < 8; ++i)
#pragma unroll
                for (int j = 0; j < 8; ++j) acc[i][j] += a[i] * bb[j];
        }
    }
#pragma unroll
    for (int i = 0; i < 8; ++i) {
        const int row = (i < 4) ? ((tm << 2) + i) : (64 + (tm << 2) + i - 4);
        float4 o0 = {acc[i][0], acc[i][1], acc[i][2], acc[i][3]};
        float4 o1 = {acc[i][4], acc[i][5], acc[i][6], acc[i][7]};
        *(float4*)(out + (size_t)row * K_ + (tn << 2)) = o0;
        *(float4*)(out + (size_t)row * K_ + 64 + (tn << 2)) = o1;
    }
}

// ---------------------------------------------------------------------------
// Blocked LDL^T (R11 variant)
// ---------------------------------------------------------------------------
__global__ __launch_bounds__(256, 1)
void factor()
{
    __shared__ float M[K_ * LDI];
    __shared__ float Wd[96 * 33];
    __shared__ float sinvd[K_];
    const int b = blockIdx.x, tid = threadIdx.x;

    const float* X0 = g_AA2 + ((size_t)(0 * B_ + b) * K_) * K_;
    const float* X1 = g_AA2 + ((size_t)(2 * B_ + b) * K_) * K_;
    for (int idx = tid; idx < K_ * K_; idx += 256) {
        const int m = idx >> 7, c = idx & 127;
        M[m * LDI + c] = X0[idx] + X1[idx];
    }
    __syncthreads();

#pragma unroll
    for (int kb = 0; kb < 4; ++kb) {
        const int j0 = kb << 5;
        if (tid < 32) {
            for (int j = 0; j < 32; ++j) {
                const float inv = __frcp_rn(M[(j0 + j) * LDI + j0 + j]);
                if (tid > j) {
                    const float cf = M[(j0 + tid) * LDI + j0 + j] * inv;
                    for (int l = j + 1; l <= tid; ++l)
                        M[(j0 + tid) * LDI + j0 + l] -= cf * M[(j0 + l) * LDI + j0 + j];
                }
                __syncwarp();
            }
            sinvd[j0 + tid] = __frcp_rn(M[(j0 + tid) * LDI + j0 + tid]);
        }
        __syncthreads();

        const int nrows = 96 - (kb << 5);
        if (nrows > 0) {
            if (tid < nrows) {
                const int i = j0 + 32 + tid;
                float w[32];
#pragma unroll
                for (int l = 0; l < 32; ++l) w[l] = M[i * LDI + j0 + l];
#pragma unroll
                for (int l = 0; l < 32; ++l) {
                    const float c = w[l] * sinvd[j0 + l];
#pragma unroll
                    for (int j = l + 1; j < 32; ++j)
                        w[j] -= c * M[(j0 + j) * LDI + j0 + l];
                }
#pragma unroll
                for (int l = 0; l < 32; ++l) {
                    M[i * LDI + j0 + l] = w[l] * sinvd[j0 + l];
                    Wd[tid * 33 + l] = w[l];
                }
            }
            __syncthreads();

            const int nb = nrows >> 1;
            for (int e = tid; e < nb * nb; e += 256) {
                const int rb = e / nb, cb = e % nb;
                if (cb <= rb) {
                    const int i0 = j0 + 32 + rb * 2, c0 = j0 + 32 + cb * 2;
                    float s00 = 0.f, s01 = 0.f, s10 = 0.f, s11 = 0.f;
#pragma unroll
                    for (int l = 0; l < 32; ++l) {
                        const float m0 = M[i0 * LDI + j0 + l];
                        const float m1 = M[(i0 + 1) * LDI + j0 + l];
                        const float w0 = Wd[(cb * 2) * 33 + l];
                        const float w1 = Wd[(cb * 2 + 1) * 33 + l];
                        s00 += m0 * w0; s01 += m0 * w1;
                        s10 += m1 * w0; s11 += m1 * w1;
                    }
                    M[i0 * LDI + c0]           -= s00;
                    M[i0 * LDI + c0 + 1]       -= s01;
                    M[(i0 + 1) * LDI + c0]     -= s10;
                    M[(i0 + 1) * LDI + c0 + 1] -= s11;
                }
            }
            __syncthreads();
        }
    }

    float* Lc = g_Lc + (size_t)b * K_ * K_;
    for (int idx = tid; idx < K_ * K_; idx += 256) {
        const int j = idx >> 7, r = idx & 127;
        float v;
        if (r < j)       v = 0.0f;
        else if (r == j) v = 1.0f;
        else if ((r >> 5) == (j >> 5)) v = M[r * LDI + j] * sinvd[j];
        else             v = M[r * LDI + j];
        Lc[idx] = v;
    }
    if (tid < K_) g_invd[b * K_ + tid] = sinvd[tid];
}

__global__ __launch_bounds__(128)
void bigsolve(const float* __restrict__ evx, const float* __restrict__ evy,
              float* __restrict__ outp)
{
    extern __shared__ float Ls[];
    __shared__ float sinvd[K_];

    const int b = blockIdx.x >> 5, grp = blockIdx.x & 31;
    const int tid = threadIdx.x, w = tid >> 5, k = tid & 31;
    const int i = grp * 4 + w;

    const float* Lc = g_Lc + (size_t)b * K_ * K_;
    for (int idx = tid; idx < K_ * K_; idx += 128) {
        const int j = idx >> 7, t = idx & 127;
        Ls[j * LDI + t] = Lc[idx];
    }
    if (tid < K_) sinvd[tid] = g_invd[b * K_ + tid];

    float r[4], d[4], x[4], invd_r[4];
    const float s = fmaxf(evx[b * K_ + K_ - 1], evy[b * K_ + K_ - 1]);
    const float g2 = sqrtf(evy[b * K_ + i] / s);
    const float h2 = 1.0f / (g2 * g2 + 1.0f);
    const float ya = g2 * h2, yb = h2;
    const float* Y0 = g_AA2 + ((size_t)(1 * B_ + b) * K_ + i) * K_;
    const float* Y1 = g_AA2 + ((size_t)(3 * B_ + b) * K_ + i) * K_;
#pragma unroll
    for (int m = 0; m < 4; ++m) {
        const int t = k + 32 * m;
        r[m] = Y0[t] + Y1[t];
        const float g1 = sqrtf(evx[b * K_ + t] / s);
        const float h1 = 1.0f / (g1 * g1 + 1.0f);
        const float re = ya - g1 * h1, im = yb - h1;
        d[m] = LAMBDA * (re * re + im * im);
        x[m] = 0.0f;
    }
    __syncthreads();
#pragma unroll
    for (int m = 0; m < 4; ++m) invd_r[m] = sinvd[k + 32 * m];

    for (int it = 0; it < 3; ++it) {
        float y[4];
#pragma unroll
        for (int m = 0; m < 4; ++m) y[m] = r[m] - d[m] * x[m];
#pragma unroll
        for (int q = 0; q < 4; ++q)
            for (int j2 = 0; j2 < 32; ++j2) {
                const int j = q * 32 + j2;
                const float yj = __shfl_sync(0xFFFFFFFFu, y[q], j2);
#pragma unroll
                for (int m = 0; m < 4; ++m)
                    if (m > q || (m == q && k > j2))
                        y[m] -= Ls[j * LDI + k + 32 * m] * yj;
            }
#pragma unroll
        for (int m = 0; m < 4; ++m) y[m] *= invd_r[m];
#pragma unroll
        for (int q = 3; q >= 0; --q)
            for (int j2 = 31; j2 >= 0; --j2) {
                const int j = q * 32 + j2;
                const float yj = __shfl_sync(0xFFFFFFFFu, y[q], j2);
#pragma unroll
                for (int m = 0; m < 4; ++m)
                    if (m < q || (m == q && k < j2))
                        y[m] -= Ls[(k + 32 * m) * LDI + j] * yj;
            }
#pragma unroll
        for (int m = 0; m < 4; ++m) x[m] = y[m];
    }
    float* o = outp + ((size_t)(b * K_ + i)) * K_;
#pragma unroll
    for (int m = 0; m < 4; ++m) o[k + 32 * m] = x[m];
}

extern "C" void kernel_launch(void* const* d_in, const int* in_sizes, int n_in,
                              void* d_out, int out_size)
{
    const float* fx  = (const float*)d_in[0];
    const float* fy  = (const float*)d_in[1];
    const float* evx = (const float*)d_in[2];
    const float* evy = (const float*)d_in[3];
    const float* ex  = (const float*)d_in[4];
    const float* ey  = (const float*)d_in[5];
    float* out = (float*)d_out;

    static cudaStream_t sA = 0;
    static cudaEvent_t evFork = 0, evJoin = 0;
    static int init_done = 0;
    if (!init_done) {
        cudaFuncSetAttribute(bigsolve, cudaFuncAttributeMaxDynamicSharedMemorySize,
                             K_ * LDI * (int)sizeof(float));
        cudaStreamCreateWithFlags(&sA, cudaStreamNonBlocking);
        cudaEventCreateWithFlags(&evFork, cudaEventDisableTiming);
        cudaEventCreateWithFlags(&evJoin, cudaEventDisableTiming);
        init_done = 1;
    }

    float* px; cudaGetSymbolAddress((void**)&px, g_part1x);
    float* py; cudaGetSymbolAddress((void**)&py, g_part1y);
    float* ax; cudaGetSymbolAddress((void**)&ax, g_Ax);
    float* ay; cudaGetSymbolAddress((void**)&ay, g_Ay);

    // x side on default stream
    gemm1_mma<<<dim3(NCH, 2, 4), 256>>>(fx, ex, px);
    cudaEventRecord(evFork, 0);

    // side stream: x-chain (reduce -> AA_xx -> factor), concurrent with gemm1_y
    cudaStreamWaitEvent(sA, evFork, 0);
    reduceHalf<<<(4 * K_ * C_) / 256, 256, 0, sA>>>(px, ax);
    gemm2_t<<<dim3(2, 4), 256, 0, sA>>>(0);
    factor<<<B_, 256, 0, sA>>>();
    cudaEventRecord(evJoin, sA);

    // default stream: y side, then join and solve
    gemm1_mma<<<dim3(NCH, 2, 4), 256>>>(fy, ey, py);
    reduceHalf<<<(4 * K_ * C_) / 256, 256>>>(py, ay);
    gemm2_t<<<dim3(2, 4), 256>>>(1);
    cudaStreamWaitEvent(0, evJoin, 0);
    bigsolve<<<B_ * 32, 128, K_ * LDI * sizeof(float)>>>(evx, evy, out);
}

// round 17
// speedup vs baseline: 1.2058x; 1.1257x over previous
#include <cuda_runtime.h>
#include <cuda_fp16.h>
#include <math.h>

#define B_ 4
#define V_ 50000
#define C_ 256
#define K_ 128
#define LAMBDA 100.0f
#define NCH 38
#define TPC 83            // 38*83 = 3154 >= 3125
#define NTILES 3125
#define LDI 129

__device__ float g_part1x[(size_t)NCH * 4 * K_ * C_];
__device__ float g_part1y[(size_t)NCH * 4 * K_ * C_];
__device__ float g_Ax[4 * K_ * C_];
__device__ float g_Ay[4 * K_ * C_];
__device__ float g_AA2[2 * 2 * B_ * K_ * K_];
__device__ float g_Lc[B_ * K_ * K_];
__device__ float g_invd[B_ * K_];

__device__ __forceinline__ unsigned smem_u32(const void* p) {
    unsigned a;
    asm("{ .reg .u64 t; cvta.to.shared.u64 t, %1; cvt.u32.u64 %0, t; }" : "=r"(a) : "l"(p));
    return a;
}
// A-side: exact fp16 split (hi + lo)
__device__ __forceinline__ void cvt2h(float x, float y, unsigned& hi, unsigned& lo) {
    __half2 h = __floats2half2_rn(x, y);
    __half2 l = __floats2half2_rn(x - __half2float(__low2half(h)),
                                  y - __half2float(__high2half(h)));
    hi = *(unsigned*)&h;
    lo = *(unsigned*)&l;
}
// B-side: single fp16 rounding
__device__ __forceinline__ unsigned cvt1h(float x, float y) {
    __half2 h = __floats2half2_rn(x, y);
    return *(unsigned*)&h;
}
__device__ __forceinline__ void ldx4(unsigned* r, unsigned a) {
    asm volatile("ldmatrix.sync.aligned.m8n8.x4.shared.b16 {%0,%1,%2,%3}, [%4];"
                 : "=r"(r[0]), "=r"(r[1]), "=r"(r[2]), "=r"(r[3]) : "r"(a));
}
__device__ __forceinline__ void ldx2t(unsigned* r, unsigned a) {
    asm volatile("ldmatrix.sync.aligned.m8n8.x2.trans.shared.b16 {%0,%1}, [%2];"
                 : "=r"(r[0]), "=r"(r[1]) : "r"(a));
}
__device__ __forceinline__ void mma16816h(float* d, const unsigned* a, const unsigned* b) {
    asm volatile("mma.sync.aligned.m16n8k16.row.col.f32.f16.f16.f32 "
                 "{%0,%1,%2,%3}, {%4,%5,%6,%7}, {%8,%9}, {%0,%1,%2,%3};"
                 : "+f"(d[0]), "+f"(d[1]), "+f"(d[2]), "+f"(d[3])
                 : "r"(a[0]), "r"(a[1]), "r"(a[2]), "r"(a[3]), "r"(b[0]), "r"(b[1]));
}

// ---------------------------------------------------------------------------
// GEMM1 (one side) via mma.sync fp16, 2 passes: D = (Ah + Al) * Bh.
// A split exactly; B rounded once (error ~2^-12, iid -> rel ~2e-4 final).
// ---------------------------------------------------------------------------
__global__ __launch_bounds__(256, 2)
void gemm1_mma(const float* __restrict__ F_, const float* __restrict__ E_,
               float* __restrict__ part)
{
    __shared__ __align__(16) __half Ah[128 * 24], Al[128 * 24];   // stride 48B
    __shared__ __align__(16) __half Bh[16 * 136];                 // stride 272B

    const int chunk = blockIdx.x, ntile = blockIdx.y, b = blockIdx.z;
    const float* E = E_ + (size_t)b * K_ * V_;
    const float* F = F_ + (size_t)b * V_ * C_ + ntile * 128;
    float* out = part + ((size_t)(chunk * 4 + b)) * K_ * C_ + ntile * 128;

    const int tid = threadIdx.x, wid = tid >> 5, lane = tid & 31;
    const int wm = (wid >> 1) * 32, wn = (wid & 1) * 64;

    const int ar = tid >> 1, ahalf = tid & 1;
    const int fv = tid >> 4, fc = (tid & 15) * 8;

    const unsigned aAh = smem_u32(Ah), aAl = smem_u32(Al), aBh = smem_u32(Bh);

    float acc[2][8][4];
#pragma unroll
    for (int mt = 0; mt < 2; ++mt)
#pragma unroll
        for (int nt = 0; nt < 8; ++nt)
#pragma unroll
            for (int e = 0; e < 4; ++e) acc[mt][nt][e] = 0.0f;

    const unsigned aoffH0 = aAh + (wm + (lane & 15)) * 48 + (lane >> 4) * 16;
    const unsigned aoffL0 = aAl + (wm + (lane & 15)) * 48 + (lane >> 4) * 16;
    const unsigned brow = (lane & 15);

    const int t0 = chunk * TPC;
    const int t1 = (t0 + TPC < NTILES) ? (t0 + TPC) : NTILES;

    const float* Ebase = E + (size_t)ar * V_ + ahalf * 8;

    float4 e0, e1, f0, f1;
    {
        const int vb = t0 << 4;
        e0 = *(const float4*)(Ebase + vb);
        e1 = *(const float4*)(Ebase + vb + 4);
        const float* Fp = F + (size_t)(vb + fv) * C_ + fc;
        f0 = *(const float4*)(Fp);
        f1 = *(const float4*)(Fp + 4);
    }

    for (int t = t0; t < t1; ++t) {
        __syncthreads();
        {
            unsigned h[4], l[4];
            cvt2h(e0.x, e0.y, h[0], l[0]); cvt2h(e0.z, e0.w, h[1], l[1]);
            cvt2h(e1.x, e1.y, h[2], l[2]); cvt2h(e1.z, e1.w, h[3], l[3]);
            *(uint4*)((char*)Ah + ar * 48 + ahalf * 16) = make_uint4(h[0], h[1], h[2], h[3]);
            *(uint4*)((char*)Al + ar * 48 + ahalf * 16) = make_uint4(l[0], l[1], l[2], l[3]);
            unsigned bh0 = cvt1h(f0.x, f0.y), bh1 = cvt1h(f0.z, f0.w);
            unsigned bh2 = cvt1h(f1.x, f1.y), bh3 = cvt1h(f1.z, f1.w);
            *(uint4*)((char*)Bh + fv * 272 + fc * 2) = make_uint4(bh0, bh1, bh2, bh3);
        }
        __syncthreads();

        if (t + 1 < t1) {
            const int vb = (t + 1) << 4;
            e0 = *(const float4*)(Ebase + vb);
            e1 = *(const float4*)(Ebase + vb + 4);
            const float* Fp = F + (size_t)(vb + fv) * C_ + fc;
            f0 = *(const float4*)(Fp);
            f1 = *(const float4*)(Fp + 4);
        }

        unsigned ahf[2][4], alf[2][4];
        ldx4(ahf[0], aoffH0);
        ldx4(ahf[1], aoffH0 + 16 * 48);
        ldx4(alf[0], aoffL0);
        ldx4(alf[1], aoffL0 + 16 * 48);
#pragma unroll
        for (int nt = 0; nt < 8; ++nt) {
            const unsigned boff = brow * 272 + (wn + nt * 8) * 2;
            unsigned bh[2];
            ldx2t(bh, aBh + boff);
#pragma unroll
            for (int mt = 0; mt < 2; ++mt) {
                mma16816h(acc[mt][nt], ahf[mt], bh);
                mma16816h(acc[mt][nt], alf[mt], bh);
            }
        }
    }

#pragma unroll
    for (int mt = 0; mt < 2; ++mt)
#pragma unroll
        for (int nt = 0; nt < 8; ++nt) {
            const int row = wm + mt * 16 + (lane >> 2);
            const int col = wn + nt * 8 + (lane & 3) * 2;
            *(float2*)(out + (size_t)row * C_ + col) =
                make_float2(acc[mt][nt][0], acc[mt][nt][1]);
            *(float2*)(out + (size_t)(row + 8) * C_ + col) =
                make_float2(acc[mt][nt][2], acc[mt][nt][3]);
        }
}

__global__ void reduceHalf(const float* __restrict__ part, float* __restrict__ outA)
{
    const int i = blockIdx.x * 256 + threadIdx.x;   // 4*K_*C_ = 131072
    float s = 0.0f;
#pragma unroll
    for (int c = 0; c < NCH; ++c) s += part[(size_t)c * 4 * K_ * C_ + i];
    outA[i] = s;
}

// gemm2 for one t: t=0 -> AA_xx (P=Q=Ax), t=1 -> AA_yx (P=Ay, Q=Ax)
__global__ __launch_bounds__(256, 2)
void gemm2_t(int t)
{
    const int cc = blockIdx.x, b = blockIdx.y;
    const float* P = (t ? g_Ay : g_Ax) + ((size_t)b * K_) * C_ + cc * 128;
    const float* Q = g_Ax + ((size_t)b * K_) * C_ + cc * 128;
    float* out = g_AA2 + ((size_t)((cc * 2 + t) * B_ + b) * K_) * K_;

    __shared__ float Ps[16][132];
    __shared__ float Qs[16][132];
    const int tid = threadIdx.x;
    const int lk = tid >> 1, lq = tid & 1;
    const int tm = tid >> 4, tn = tid & 15;

    float acc[8][8];
#pragma unroll
    for (int i = 0; i < 8; ++i)
#pragma unroll
        for (int j = 0; j < 8; ++j) acc[i][j] = 0.0f;

    for (int kt = 0; kt < 8; ++kt) {
        const int c = kt << 4;
        float4 p0 = *(const float4*)(P + (size_t)lk * C_ + c + (lq << 2));
        float4 p1 = *(const float4*)(P + (size_t)lk * C_ + c + (lq << 2) + 8);
        float4 q0 = *(const float4*)(Q + (size_t)lk * C_ + c + (lq << 2));
        float4 q1 = *(const float4*)(Q + (size_t)lk * C_ + c + (lq << 2) + 8);
        __syncthreads();
        const int r0 = lq << 2;
        Ps[r0 + 0][lk] = p0.x; Ps[r0 + 1][lk] = p0.y; Ps[r0 + 2][lk] = p0.z; Ps[r0 + 3][lk] = p0.w;
        Ps[r0 + 8][lk] = p1.x; Ps[r0 + 9][lk] = p1.y; Ps[r0 + 10][lk] = p1.z; Ps[r0 + 11][lk] = p1.w;
        Qs[r0 + 0][lk] = q0.x; Qs[r0 + 1][lk] = q0.y; Qs[r0 + 2][lk] = q0.z; Qs[r0 + 3][lk] = q0.w;
        Qs[r0 + 8][lk] = q1.x; Qs[r0 + 9][lk] = q1.y; Qs[r0 + 10][lk] = q1.z; Qs[r0 + 11][lk] = q1.w;
        __syncthreads();
#pragma unroll
        for (int vv = 0; vv < 16; ++vv) {
            float4 a0 = *(const float4*)&Ps[vv][tm << 2];
            float4 a1 = *(const float4*)&Ps[vv][64 + (tm << 2)];
            float4 b0 = *(const float4*)&Qs[vv][tn << 2];
            float4 b1 = *(const float4*)&Qs[vv][64 + (tn << 2)];
            float a[8] = {a0.x, a0.y, a0.z, a0.w, a1.x, a1.y, a1.z, a1.w};
            float bb[8] = {b0.x, b0.y, b0.z, b0.w, b1.x, b1.y, b1.z, b1.w};
#pragma unroll
            for (int i = 0; i < 8; ++i)
#pragma unroll
                for (int j = 0; j < 8; ++j) acc[i][j] += a[i] * bb[j];
        }
    }
#pragma unroll
    for (int i = 0; i < 8; ++i) {
        const int row = (i < 4) ? ((tm << 2) + i) : (64 + (tm << 2) + i - 4);
        float4 o0 = {acc[i][0], acc[i][1], acc[i][2], acc[i][3]};
        float4 o1 = {acc[i][4], acc[i][5], acc[i][6], acc[i][7]};
        *(float4*)(out + (size_t)row * K_ + (tn << 2)) = o0;
        *(float4*)(out + (size_t)row * K_ + 64 + (tn << 2)) = o1;
    }
}

// ---------------------------------------------------------------------------
// Blocked LDL^T (R11 variant). Grid padded to 148 to dodge the sm_103a
// low-grid issue throttle; blocks >= B_ exit immediately.
// ---------------------------------------------------------------------------
__global__ __launch_bounds__(256, 1)
void factor()
{
    __shared__ float M[K_ * LDI];
    __shared__ float Wd[96 * 33];
    __shared__ float sinvd[K_];
    const int b = blockIdx.x, tid = threadIdx.x;
    if (b >= B_) return;

    const float* X0 = g_AA2 + ((size_t)(0 * B_ + b) * K_) * K_;
    const float* X1 = g_AA2 + ((size_t)(2 * B_ + b) * K_) * K_;
    for (int idx = tid; idx < K_ * K_; idx += 256) {
        const int m = idx >> 7, c = idx & 127;
        M[m * LDI + c] = X0[idx] + X1[idx];
    }
    __syncthreads();

#pragma unroll
    for (int kb = 0; kb < 4; ++kb) {
        const int j0 = kb << 5;
        if (tid < 32) {
            for (int j = 0; j < 32; ++j) {
                const float inv = __frcp_rn(M[(j0 + j) * LDI + j0 + j]);
                if (tid > j) {
                    const float cf = M[(j0 + tid) * LDI + j0 + j] * inv;
                    for (int l = j + 1; l <= tid; ++l)
                        M[(j0 + tid) * LDI + j0 + l] -= cf * M[(j0 + l) * LDI + j0 + j];
                }
                __syncwarp();
            }
            sinvd[j0 + tid] = __frcp_rn(M[(j0 + tid) * LDI + j0 + tid]);
        }
        __syncthreads();

        const int nrows = 96 - (kb << 5);
        if (nrows > 0) {
            if (tid < nrows) {
                const int i = j0 + 32 + tid;
                float w[32];
#pragma unroll
                for (int l = 0; l < 32; ++l) w[l] = M[i * LDI + j0 + l];
#pragma unroll
                for (int l = 0; l < 32; ++l) {
                    const float c = w[l] * sinvd[j0 + l];
#pragma unroll
                    for (int j = l + 1; j < 32; ++j)
                        w[j] -= c * M[(j0 + j) * LDI + j0 + l];
                }
#pragma unroll
                for (int l = 0; l < 32; ++l) {
                    M[i * LDI + j0 + l] = w[l] * sinvd[j0 + l];
                    Wd[tid * 33 + l] = w[l];
                }
            }
            __syncthreads();

            const int nb = nrows >> 1;
            for (int e = tid; e < nb * nb; e += 256) {
                const int rb = e / nb, cb = e % nb;
                if (cb <= rb) {
                    const int i0 = j0 + 32 + rb * 2, c0 = j0 + 32 + cb * 2;
                    float s00 = 0.f, s01 = 0.f, s10 = 0.f, s11 = 0.f;
#pragma unroll
                    for (int l = 0; l < 32; ++l) {
                        const float m0 = M[i0 * LDI + j0 + l];
                        const float m1 = M[(i0 + 1) * LDI + j0 + l];
                        const float w0 = Wd[(cb * 2) * 33 + l];
                        const float w1 = Wd[(cb * 2 + 1) * 33 + l];
                        s00 += m0 * w0; s01 += m0 * w1;
                        s10 += m1 * w0; s11 += m1 * w1;
                    }
                    M[i0 * LDI + c0]           -= s00;
                    M[i0 * LDI + c0 + 1]       -= s01;
                    M[(i0 + 1) * LDI + c0]     -= s10;
                    M[(i0 + 1) * LDI + c0 + 1] -= s11;
                }
            }
            __syncthreads();
        }
    }

    float* Lc = g_Lc + (size_t)b * K_ * K_;
    for (int idx = tid; idx < K_ * K_; idx += 256) {
        const int j = idx >> 7, r = idx & 127;
        float v;
        if (r < j)       v = 0.0f;
        else if (r == j) v = 1.0f;
        else if ((r >> 5) == (j >> 5)) v = M[r * LDI + j] * sinvd[j];
        else             v = M[r * LDI + j];
        Lc[idx] = v;
    }
    if (tid < K_) g_invd[b * K_ + tid] = sinvd[tid];
}

__global__ __launch_bounds__(128)
void bigsolve(const float* __restrict__ evx, const float* __restrict__ evy,
              float* __restrict__ outp)
{
    extern __shared__ float Ls[];
    __shared__ float sinvd[K_];

    const int b = blockIdx.x >> 5, grp = blockIdx.x & 31;
    const int tid = threadIdx.x, w = tid >> 5, k = tid & 31;
    const int i = grp * 4 + w;

    const float* Lc = g_Lc + (size_t)b * K_ * K_;
    for (int idx = tid; idx < K_ * K_; idx += 128) {
        const int j = idx >> 7, t = idx & 127;
        Ls[j * LDI + t] = Lc[idx];
    }
    if (tid < K_) sinvd[tid] = g_invd[b * K_ + tid];

    float r[4], d[4], x[4], invd_r[4];
    const float s = fmaxf(evx[b * K_ + K_ - 1], evy[b * K_ + K_ - 1]);
    const float g2 = sqrtf(evy[b * K_ + i] / s);
    const float h2 = 1.0f / (g2 * g2 + 1.0f);
    const float ya = g2 * h2, yb = h2;
    const float* Y0 = g_AA2 + ((size_t)(1 * B_ + b) * K_ + i) * K_;
    const float* Y1 = g_AA2 + ((size_t)(3 * B_ + b) * K_ + i) * K_;
#pragma unroll
    for (int m = 0; m < 4; ++m) {
        const int t = k + 32 * m;
        r[m] = Y0[t] + Y1[t];
        const float g1 = sqrtf(evx[b * K_ + t] / s);
        const float h1 = 1.0f / (g1 * g1 + 1.0f);
        const float re = ya - g1 * h1, im = yb - h1;
        d[m] = LAMBDA * (re * re + im * im);
        x[m] = 0.0f;
    }
    __syncthreads();
#pragma unroll
    for (int m = 0; m < 4; ++m) invd_r[m] = sinvd[k + 32 * m];

    for (int it = 0; it < 3; ++it) {
        float y[4];
#pragma unroll
        for (int m = 0; m < 4; ++m) y[m] = r[m] - d[m] * x[m];
#pragma unroll
        for (int q = 0; q < 4; ++q)
            for (int j2 = 0; j2 < 32; ++j2) {
                const int j = q * 32 + j2;
                const float yj = __shfl_sync(0xFFFFFFFFu, y[q], j2);
#pragma unroll
                for (int m = 0; m < 4; ++m)
                    if (m > q || (m == q && k > j2))
                        y[m] -= Ls[j * LDI + k + 32 * m] * yj;
            }
#pragma unroll
        for (int m = 0; m < 4; ++m) y[m] *= invd_r[m];
#pragma unroll
        for (int q = 3; q >= 0; --q)
            for (int j2 = 31; j2 >= 0; --j2) {
                const int j = q * 32 + j2;
                const float yj = __shfl_sync(0xFFFFFFFFu, y[q], j2);
#pragma unroll
                for (int m = 0; m < 4; ++m)
                    if (m < q || (m == q && k < j2))
                        y[m] -= Ls[(k + 32 * m) * LDI + j] * yj;
            }
#pragma unroll
        for (int m = 0; m < 4; ++m) x[m] = y[m];
    }
    float* o = outp + ((size_t)(b * K_ + i)) * K_;
#pragma unroll
    for (int m = 0; m < 4; ++m) o[k + 32 * m] = x[m];
}

extern "C" void kernel_launch(void* const* d_in, const int* in_sizes, int n_in,
                              void* d_out, int out_size)
{
    const float* fx  = (const float*)d_in[0];
    const float* fy  = (const float*)d_in[1];
    const float* evx = (const float*)d_in[2];
    const float* evy = (const float*)d_in[3];
    const float* ex  = (const float*)d_in[4];
    const float* ey  = (const float*)d_in[5];
    float* out = (float*)d_out;

    static cudaStream_t sA = 0;
    static cudaEvent_t evFork = 0, evJoin = 0;
    static int init_done = 0;
    if (!init_done) {
        cudaFuncSetAttribute(bigsolve, cudaFuncAttributeMaxDynamicSharedMemorySize,
                             K_ * LDI * (int)sizeof(float));
        cudaStreamCreateWithFlags(&sA, cudaStreamNonBlocking);
        cudaEventCreateWithFlags(&evFork, cudaEventDisableTiming);
        cudaEventCreateWithFlags(&evJoin, cudaEventDisableTiming);
        init_done = 1;
    }

    float* px; cudaGetSymbolAddress((void**)&px, g_part1x);
    float* py; cudaGetSymbolAddress((void**)&py, g_part1y);
    float* ax; cudaGetSymbolAddress((void**)&ax, g_Ax);
    float* ay; cudaGetSymbolAddress((void**)&ay, g_Ay);

    // x side on default stream
    gemm1_mma<<<dim3(NCH, 2, 4), 256>>>(fx, ex, px);
    cudaEventRecord(evFork, 0);

    // side stream: x-chain (reduce -> AA_xx -> factor), concurrent with gemm1_y
    cudaStreamWaitEvent(sA, evFork, 0);
    reduceHalf<<<(4 * K_ * C_) / 256, 256, 0, sA>>>(px, ax);
    gemm2_t<<<dim3(2, 4), 256, 0, sA>>>(0);
    factor<<<148, 256, 0, sA>>>();
    cudaEventRecord(evJoin, sA);

    // default stream: y side, then join and solve
    gemm1_mma<<<dim3(NCH, 2, 4), 256>>>(fy, ey, py);
    reduceHalf<<<(4 * K_ * C_) / 256, 256>>>(py, ay);
    gemm2_t<<<dim3(2, 4), 256>>>(1);
    cudaStreamWaitEvent(0, evJoin, 0);
    bigsolve<<<B_ * 32, 128, K_ * LDI * sizeof(float)>>>(evx, evy, out);
}